// round 7
// baseline (speedup 1.0000x reference)
#include <cuda_runtime.h>
#include <cstdint>
#include <cstddef>

// Problem constants
#define BATCH   16
#define CIN     256
#define HH      64
#define WW      64
#define HW      4096
#define OC_QKV  768
#define HEADS   64
#define ATT_CH  512
#define OC_OUT  256
#define K_PROJ  512

// ---------------------------------------------------------------------------
// Scratch. "Paired" layout = per row, per 32-k chunk, 64 floats:
//   off = (k/8)*16 + (k%4)*4 + ((k%8)/4)*2 ; value at off, residual at off+1
// == GEMM smem tile row, so fills are raw 256B copies.
// ---------------------------------------------------------------------------
__device__ float g_qkv [(size_t)BATCH * OC_QKV * HW];     // [b][ch][n]
__device__ float g_agg [(size_t)BATCH * OC_QKV * HW];     // [b][ch][n]
__device__ float g_kv  [(size_t)BATCH * HEADS * 4 * 72];  // 4 n-segment partials
__device__ float g_attp[(size_t)BATCH * HW * 2 * ATT_CH]; // att paired [b][n][16][64]
__device__ float g_xtp [(size_t)BATCH * HW * 2 * CIN];    // x^T paired [b][n][8][64]
__device__ float g_wqp [(size_t)OC_QKV * 2 * CIN];        // w_qkv paired
__device__ float g_wpp [(size_t)OC_OUT * 2 * K_PROJ];     // w_proj paired

// ---------------------------------------------------------------------------
// Helpers
// ---------------------------------------------------------------------------
__device__ __forceinline__ float tf32r(float x) {
    float r;
    asm("cvt.rna.tf32.f32 %0, %1;" : "=f"(r) : "f"(x));
    return r;
}
__device__ __forceinline__ int pair_off(int kk) {
    return (kk >> 3) * 16 + (kk & 3) * 4 + ((kk >> 2) & 1) * 2;
}
__device__ __forceinline__ void mma_tf32(float* d, const uint32_t* a, const uint32_t* b) {
    asm volatile(
        "mma.sync.aligned.m16n8k8.row.col.f32.tf32.tf32.f32 "
        "{%0,%1,%2,%3}, {%4,%5,%6,%7}, {%8,%9}, {%0,%1,%2,%3};"
        : "+f"(d[0]), "+f"(d[1]), "+f"(d[2]), "+f"(d[3])
        : "r"(a[0]), "r"(a[1]), "r"(a[2]), "r"(a[3]), "r"(b[0]), "r"(b[1]));
}
#define CP_ASYNC16(sa, gp) \
    asm volatile("cp.async.ca.shared.global [%0], [%1], 16;" :: "r"(sa), "l"(gp))
#define CP_COMMIT() asm volatile("cp.async.commit_group;")
#define CP_WAIT_ALL() asm volatile("cp.async.wait_group 0;")

// ---------------------------------------------------------------------------
// Weight splitter -> paired layout [m][K/32][64]
// ---------------------------------------------------------------------------
__global__ __launch_bounds__(256)
void split_kernel(const float* __restrict__ in, float* __restrict__ out, int M, int K)
{
    const int i = blockIdx.x * 256 + threadIdx.x;
    if (i >= M * K) return;
    const int m = i / K;
    const int k = i - m * K;
    const float v = in[i];
    const float h = tf32r(v);
    float* dst = out + ((size_t)m * (K >> 5) + (k >> 5)) * 64 + pair_off(k & 31);
    dst[0] = h;
    dst[1] = tf32r(v - h);
}

// ---------------------------------------------------------------------------
// tf32 mma.sync GEMM, operands pre-split + pre-permuted, cp.async 2-stage.
// TP=68: row stride 272B == 16 mod 128 -> conflict-free LDS.128 frags + STS.
// Block 128x128, K-chunk 32, 8 warps each 32(M) x 64(N).
// ---------------------------------------------------------------------------
#define TP 68
#define STG (2 * 128 * TP)                 // floats per stage
#define GEMM_SMEM (2 * STG * 4)            // 139264 bytes

__global__ __launch_bounds__(256, 1)
void gemm_pair(const float* __restrict__ Ap, const float* __restrict__ Bp,
               float* __restrict__ C, int M, int nch,
               const float* __restrict__ gamma, const float* __restrict__ beta,
               const float* __restrict__ mean,  const float* __restrict__ var)
{
    extern __shared__ float sm[];
    const int tid  = threadIdx.x;
    const int wid  = tid >> 5;
    const int lane = tid & 31;
    const int g    = lane >> 2;
    const int tig  = lane & 3;

    const int n0 = blockIdx.x * 128;
    const int m0 = blockIdx.y * 128;
    const int z  = blockIdx.z;

    const int wm = (wid & 3) * 32;
    const int wn = (wid >> 2) * 64;

    const float* Bb = Bp + (size_t)z * HW * (size_t)(nch * 64);
    float*       Cb = C  + (size_t)z * M * HW;

    uint32_t smb;
    asm("{ .reg .u64 t; cvta.to.shared.u64 t, %1; cvt.u32.u64 %0, t; }" : "=r"(smb) : "l"(sm));

    const int frow = tid & 127;
    const int isB  = tid >> 7;
    const float* gsrc0 = isB ? (Bb + (size_t)(n0 + frow) * (nch * 64))
                             : (Ap + (size_t)(m0 + frow) * (nch * 64));
    const uint32_t sdst0 = smb + (uint32_t)(isB * 128 * TP + frow * TP) * 4u;

    float acc[2][8][4];
    #pragma unroll
    for (int mt = 0; mt < 2; mt++)
        #pragma unroll
        for (int nt = 0; nt < 8; nt++)
            #pragma unroll
            for (int j = 0; j < 4; j++) acc[mt][nt][j] = 0.f;

    // prologue: chunk 0 -> stage 0
    {
        const float* s = gsrc0;
        #pragma unroll
        for (int u = 0; u < 16; u++) CP_ASYNC16(sdst0 + u * 16, s + u * 4);
        CP_COMMIT();
    }

    for (int c = 0; c < nch; c++) {
        CP_WAIT_ALL();
        __syncthreads();
        if (c + 1 < nch) {
            const float* s = gsrc0 + (size_t)(c + 1) * 64;
            const uint32_t d = sdst0 + ((uint32_t)((c + 1) & 1)) * (STG * 4u);
            #pragma unroll
            for (int u = 0; u < 16; u++) CP_ASYNC16(d + u * 16, s + u * 4);
            CP_COMMIT();
        }
        const float* As_ = sm + (c & 1) * STG;
        const float* Bs_ = As_ + 128 * TP;

        #pragma unroll
        for (int ks = 0; ks < 4; ks++) {
            const int col = ks * 16 + tig * 4;
            uint32_t bh[8][2], bl[8][2];
            #pragma unroll
            for (int nt = 0; nt < 8; nt++) {
                float4 rb = *(const float4*)(Bs_ + (wn + nt * 8 + g) * TP + col);
                bh[nt][0] = __float_as_uint(rb.x);
                bl[nt][0] = __float_as_uint(rb.y);
                bh[nt][1] = __float_as_uint(rb.z);
                bl[nt][1] = __float_as_uint(rb.w);
            }
            #pragma unroll
            for (int mt = 0; mt < 2; mt++) {
                const int mr = wm + mt * 16;
                float4 r1 = *(const float4*)(As_ + (mr + g    ) * TP + col);
                float4 r2 = *(const float4*)(As_ + (mr + 8 + g) * TP + col);
                uint32_t ahi[4] = { __float_as_uint(r1.x), __float_as_uint(r2.x),
                                    __float_as_uint(r1.z), __float_as_uint(r2.z) };
                uint32_t alo[4] = { __float_as_uint(r1.y), __float_as_uint(r2.y),
                                    __float_as_uint(r1.w), __float_as_uint(r2.w) };
                #pragma unroll
                for (int nt = 0; nt < 8; nt++) {
                    mma_tf32(acc[mt][nt], alo, bh[nt]);   // Al*Bh
                    mma_tf32(acc[mt][nt], ahi, bl[nt]);   // Ah*Bl
                    mma_tf32(acc[mt][nt], ahi, bh[nt]);   // Ah*Bh
                }
            }
        }
    }

    // epilogue
    #pragma unroll
    for (int mt = 0; mt < 2; mt++) {
        const int mA = m0 + wm + mt * 16 + g;
        const int mB = mA + 8;
        float sA = 1.f, hA = 0.f, sB = 1.f, hB = 0.f;
        if (gamma) {
            float invA = gamma[mA] * rsqrtf(var[mA] + 1e-5f);
            float invB = gamma[mB] * rsqrtf(var[mB] + 1e-5f);
            sA = invA; hA = beta[mA] - mean[mA] * invA;
            sB = invB; hB = beta[mB] - mean[mB] * invB;
        }
        float* rowA = Cb + (size_t)mA * HW + n0 + wn + 2 * tig;
        float* rowB = Cb + (size_t)mB * HW + n0 + wn + 2 * tig;
        #pragma unroll
        for (int nt = 0; nt < 8; nt++) {
            float2 oA, oB;
            oA.x = acc[mt][nt][0] * sA + hA;
            oA.y = acc[mt][nt][1] * sA + hA;
            oB.x = acc[mt][nt][2] * sB + hB;
            oB.y = acc[mt][nt][3] * sB + hB;
            *(float2*)(rowA + nt * 8) = oA;
            *(float2*)(rowB + nt * 8) = oB;
        }
    }
}

// ---------------------------------------------------------------------------
// Transpose x: [b][k=256][n] -> paired xt [b][n][8][64]
// ---------------------------------------------------------------------------
__global__ __launch_bounds__(256)
void transpose_kernel(const float* __restrict__ in, float* __restrict__ outp)
{
    __shared__ float t[32][33];
    const int b  = blockIdx.z;
    const int n0 = blockIdx.x * 32;
    const int k0 = blockIdx.y * 32;
    const int tx = threadIdx.x & 31;
    const int ty = threadIdx.x >> 5;

    const float* ib = in + (size_t)b * CIN * HW;
    float* ob = outp + (size_t)b * HW * (2 * CIN);

    #pragma unroll
    for (int i = 0; i < 4; i++) {
        const int k = k0 + ty + i * 8;
        t[ty + i * 8][tx] = ib[(size_t)k * HW + n0 + tx];
    }
    __syncthreads();
    #pragma unroll
    for (int i = 0; i < 4; i++) {
        const int n = n0 + ty + i * 8;
        const int k = k0 + tx;
        const float v = t[tx][ty + i * 8];
        const float h = tf32r(v);
        float* dst = ob + (size_t)n * (2 * CIN) + (k >> 5) * 64 + pair_off(k & 31);
        dst[0] = h;
        dst[1] = tf32r(v - h);
    }
}

// ---------------------------------------------------------------------------
// Fused depthwise 3x3 + grouped 1x1
// ---------------------------------------------------------------------------
__global__ __launch_bounds__(256)
void dwpw_kernel(const float* __restrict__ qkv,
                 const float* __restrict__ wdw,
                 const float* __restrict__ wpw,
                 float* __restrict__ agg)
{
    const int strip = blockIdx.x;
    const int gg    = blockIdx.y;
    const int b     = blockIdx.z;
    const int r0    = strip * 16;

    __shared__ float s_in[8][18][68];
    __shared__ float s_wdw[8][9];
    __shared__ float s_wpw[8][8];

    const int tid = threadIdx.x;
    const float* base = qkv + ((size_t)b * OC_QKV + gg * 8) * HW;

    for (int idx = tid; idx < 8 * 18 * 16; idx += 256) {
        const int seg = idx & 15;
        const int row = idx >> 4;
        const int rr  = row % 18;
        const int ch  = row / 18;
        const int y   = r0 + rr - 1;
        float4 v = make_float4(0.f, 0.f, 0.f, 0.f);
        if (y >= 0 && y < HH)
            v = *(const float4*)(base + (size_t)ch * HW + y * WW + seg * 4);
        float* d = &s_in[ch][rr][1 + seg * 4];
        d[0] = v.x; d[1] = v.y; d[2] = v.z; d[3] = v.w;
        if (seg == 0)  s_in[ch][rr][0]  = 0.f;
        if (seg == 15) s_in[ch][rr][65] = 0.f;
    }
    if (tid < 72)
        s_wdw[tid / 9][tid % 9] = wdw[(size_t)(gg * 8 + tid / 9) * 9 + tid % 9];
    if (tid >= 128 && tid < 192) {
        int t = tid - 128;
        s_wpw[t >> 3][t & 7] = wpw[(size_t)(gg * 8 + (t >> 3)) * 8 + (t & 7)];
    }
    __syncthreads();

    float* obase = agg + ((size_t)b * OC_QKV + gg * 8) * HW + r0 * WW;
    for (int p = tid; p < 16 * WW; p += 256) {
        const int py = p >> 6;
        const int px = p & 63;
        float dwv[8];
        #pragma unroll
        for (int ic = 0; ic < 8; ic++) {
            float s = 0.f;
            #pragma unroll
            for (int ky = 0; ky < 3; ky++)
                #pragma unroll
                for (int kx = 0; kx < 3; kx++)
                    s += s_in[ic][py + ky][px + kx] * s_wdw[ic][ky * 3 + kx];
            dwv[ic] = s;
        }
        #pragma unroll
        for (int oc = 0; oc < 8; oc++) {
            float s = 0.f;
            #pragma unroll
            for (int ic = 0; ic < 8; ic++) s += s_wpw[oc][ic] * dwv[ic];
            obase[(size_t)oc * HW + p] = s;
        }
    }
}

// ---------------------------------------------------------------------------
// kv partial reduction over an n-segment (grid.z = 4 segments of 1024)
// ---------------------------------------------------------------------------
__global__ __launch_bounds__(256)
void kv_kernel(const float* __restrict__ qkv, const float* __restrict__ agg,
               float* __restrict__ kvout)
{
    const int h   = blockIdx.x;
    const int b   = blockIdx.y;
    const int seg = blockIdx.z;
    const float* src = (h < 32) ? qkv : agg;
    const int ch0 = (h & 31) * 24;
    const float* base = src + ((size_t)b * OC_QKV + ch0) * HW;

    float acc[8][9];
    #pragma unroll
    for (int d = 0; d < 8; d++)
        #pragma unroll
        for (int e = 0; e < 9; e++) acc[d][e] = 0.f;

    const int nend = (seg + 1) * 1024;
    for (int n = seg * 1024 + threadIdx.x; n < nend; n += 256) {
        float kk[8], vv[8];
        #pragma unroll
        for (int d = 0; d < 8; d++)
            kk[d] = fmaxf(base[(size_t)(8 + d) * HW + n], 0.f);
        #pragma unroll
        for (int e = 0; e < 8; e++)
            vv[e] = base[(size_t)(16 + e) * HW + n];
        #pragma unroll
        for (int d = 0; d < 8; d++) {
            #pragma unroll
            for (int e = 0; e < 8; e++) acc[d][e] += kk[d] * vv[e];
            acc[d][8] += kk[d];
        }
    }

    __shared__ float sred[8][72];
    const int lane = threadIdx.x & 31;
    const int warp = threadIdx.x >> 5;
    #pragma unroll
    for (int d = 0; d < 8; d++)
        #pragma unroll
        for (int e = 0; e < 9; e++) {
            float v = acc[d][e];
            #pragma unroll
            for (int o = 16; o > 0; o >>= 1)
                v += __shfl_down_sync(0xffffffffu, v, o);
            if (lane == 0) sred[warp][d * 9 + e] = v;
        }
    __syncthreads();
    if (threadIdx.x < 72) {
        float s = 0.f;
        #pragma unroll
        for (int w = 0; w < 8; w++) s += sred[w][threadIdx.x];
        kvout[(((size_t)b * HEADS + h) * 4 + seg) * 72 + threadIdx.x] = s;
    }
}

// ---------------------------------------------------------------------------
// attention apply -> writes paired att [b][n][16][64] (GEMM2 B layout)
// ---------------------------------------------------------------------------
__global__ __launch_bounds__(256)
void apply_kernel(const float* __restrict__ qkv, const float* __restrict__ agg,
                  const float* __restrict__ kvin, float* __restrict__ attp)
{
    const int h = blockIdx.x;
    const int b = blockIdx.y;
    const float* src = (h < 32) ? qkv : agg;
    const int ch0 = (h & 31) * 24;
    const float* qb = src + ((size_t)b * OC_QKV + ch0) * HW;

    __shared__ float s_kv[72];
    if (threadIdx.x < 72) {
        const float* kp = kvin + ((size_t)b * HEADS + h) * 4 * 72 + threadIdx.x;
        s_kv[threadIdx.x] = kp[0] + kp[72] + kp[144] + kp[216];
    }
    __syncthreads();

    float* ob = attp + (size_t)b * HW * (2 * ATT_CH) + (h >> 2) * 64 + (h & 3) * 16;
    for (int n = threadIdx.x; n < HW; n += 256) {
        float q[8];
        #pragma unroll
        for (int d = 0; d < 8; d++)
            q[d] = fmaxf(qb[(size_t)d * HW + n], 0.f);
        float num[9];
        #pragma unroll
        for (int e = 0; e < 9; e++) {
            float s = 0.f;
            #pragma unroll
            for (int d = 0; d < 8; d++) s += q[d] * s_kv[d * 9 + e];
            num[e] = s;
        }
        const float r = 1.0f / (num[8] + 1e-15f);
        float hv[8], lv[8];
        #pragma unroll
        for (int d = 0; d < 8; d++) {
            const float v = num[d] * r;
            hv[d] = tf32r(v);
            lv[d] = tf32r(v - hv[d]);
        }
        float* dst = ob + (size_t)n * (2 * ATT_CH);
        *(float4*)(dst + 0)  = make_float4(hv[0], lv[0], hv[4], lv[4]);
        *(float4*)(dst + 4)  = make_float4(hv[1], lv[1], hv[5], lv[5]);
        *(float4*)(dst + 8)  = make_float4(hv[2], lv[2], hv[6], lv[6]);
        *(float4*)(dst + 12) = make_float4(hv[3], lv[3], hv[7], lv[7]);
    }
}

// ---------------------------------------------------------------------------
// Launch
// ---------------------------------------------------------------------------
extern "C" void kernel_launch(void* const* d_in, const int* in_sizes, int n_in,
                              void* d_out, int out_size)
{
    const float* x      = (const float*)d_in[0];
    const float* w_qkv  = (const float*)d_in[1];
    const float* w_dw   = (const float*)d_in[2];
    const float* w_pw   = (const float*)d_in[3];
    const float* w_proj = (const float*)d_in[4];
    const float* gamma  = (const float*)d_in[5];
    const float* beta   = (const float*)d_in[6];
    const float* mean   = (const float*)d_in[7];
    const float* var    = (const float*)d_in[8];
    float* out = (float*)d_out;

    float *qkv_p, *agg_p, *kv_p, *attp_p, *xtp_p, *wqp_p, *wpp_p;
    cudaGetSymbolAddress((void**)&qkv_p,  g_qkv);
    cudaGetSymbolAddress((void**)&agg_p,  g_agg);
    cudaGetSymbolAddress((void**)&kv_p,   g_kv);
    cudaGetSymbolAddress((void**)&attp_p, g_attp);
    cudaGetSymbolAddress((void**)&xtp_p,  g_xtp);
    cudaGetSymbolAddress((void**)&wqp_p,  g_wqp);
    cudaGetSymbolAddress((void**)&wpp_p,  g_wpp);

    cudaFuncSetAttribute(gemm_pair, cudaFuncAttributeMaxDynamicSharedMemorySize, GEMM_SMEM);

    // 0) split weights + transpose/split x into paired layouts
    split_kernel<<<(OC_QKV * CIN + 255) / 256, 256>>>(w_qkv, wqp_p, OC_QKV, CIN);
    split_kernel<<<(OC_OUT * K_PROJ + 255) / 256, 256>>>(w_proj, wpp_p, OC_OUT, K_PROJ);
    {
        dim3 grid(HW / 32, CIN / 32, BATCH);
        transpose_kernel<<<grid, 256>>>(x, xtp_p);
    }
    // 1) qkv = W_qkv * x : M=768, nch=8
    {
        dim3 grid(HW / 128, OC_QKV / 128, BATCH);
        gemm_pair<<<grid, 256, GEMM_SMEM>>>(wqp_p, xtp_p, qkv_p, OC_QKV, CIN / 32,
                                            nullptr, nullptr, nullptr, nullptr);
    }
    // 2) depthwise + grouped pointwise
    {
        dim3 grid(4, 96, BATCH);
        dwpw_kernel<<<grid, 256>>>(qkv_p, w_dw, w_pw, agg_p);
    }
    // 3) kv partial reduction (4 segments)
    {
        dim3 grid(HEADS, BATCH, 4);
        kv_kernel<<<grid, 256>>>(qkv_p, agg_p, kv_p);
    }
    // 4) attention apply (writes paired att)
    {
        dim3 grid(HEADS, BATCH);
        apply_kernel<<<grid, 256>>>(qkv_p, agg_p, kv_p, attp_p);
    }
    // 5) y = W_proj * att + BN : M=256, nch=16
    {
        dim3 grid(HW / 128, OC_OUT / 128, BATCH);
        gemm_pair<<<grid, 256, GEMM_SMEM>>>(wpp_p, attp_p, out, OC_OUT, K_PROJ / 32,
                                            gamma, beta, mean, var);
    }
}

// round 8
// speedup vs baseline: 1.3169x; 1.3169x over previous
#include <cuda_runtime.h>
#include <cstdint>
#include <cstddef>

// Problem constants
#define BATCH   16
#define CIN     256
#define HH      64
#define WW      64
#define HW      4096
#define OC_QKV  768
#define HEADS   64
#define ATT_CH  512
#define OC_OUT  256
#define K_PROJ  512

// ---------------------------------------------------------------------------
// Paired layout, 16-k chunks: per row, per chunk, 32 floats:
//   off(kk) = (kk/8)*16 + (kk%4)*4 + ((kk%8)/4)*2 ; hi at off, lo at off+1
// ---------------------------------------------------------------------------
__device__ float g_qkv [(size_t)BATCH * OC_QKV * HW];
__device__ float g_agg [(size_t)BATCH * OC_QKV * HW];
__device__ float g_kv  [(size_t)BATCH * HEADS * 4 * 72];
__device__ float g_attp[(size_t)BATCH * HW * 2 * ATT_CH]; // [b][n][32ch][32]
__device__ float g_xtp [(size_t)BATCH * HW * 2 * CIN];    // [b][n][16ch][32]
__device__ float g_wqp [(size_t)OC_QKV * 2 * CIN];
__device__ float g_wpp [(size_t)OC_OUT * 2 * K_PROJ];

// ---------------------------------------------------------------------------
// Helpers
// ---------------------------------------------------------------------------
__device__ __forceinline__ float tf32r(float x) {
    float r;
    asm("cvt.rna.tf32.f32 %0, %1;" : "=f"(r) : "f"(x));
    return r;
}
__device__ __forceinline__ int pair16(int kk) {   // kk in 0..15
    return ((kk >> 3) << 4) + ((kk & 3) << 2) + (((kk >> 2) & 1) << 1);
}
__device__ __forceinline__ void mma_tf32(float* d, const uint32_t* a, const uint32_t* b) {
    asm volatile(
        "mma.sync.aligned.m16n8k8.row.col.f32.tf32.tf32.f32 "
        "{%0,%1,%2,%3}, {%4,%5,%6,%7}, {%8,%9}, {%0,%1,%2,%3};"
        : "+f"(d[0]), "+f"(d[1]), "+f"(d[2]), "+f"(d[3])
        : "r"(a[0]), "r"(a[1]), "r"(a[2]), "r"(a[3]), "r"(b[0]), "r"(b[1]));
}
#define CP_ASYNC16(sa, gp) \
    asm volatile("cp.async.ca.shared.global [%0], [%1], 16;" :: "r"(sa), "l"(gp))
#define CP_COMMIT() asm volatile("cp.async.commit_group;")
#define CP_WAIT_ALL() asm volatile("cp.async.wait_group 0;")

// ---------------------------------------------------------------------------
// Weight splitter -> paired layout [m][K/16][32]
// ---------------------------------------------------------------------------
__global__ __launch_bounds__(256)
void split_kernel(const float* __restrict__ in, float* __restrict__ out, int M, int K)
{
    const int i = blockIdx.x * 256 + threadIdx.x;
    if (i >= M * K) return;
    const int m = i / K;
    const int k = i - m * K;
    const float v = in[i];
    const float h = tf32r(v);
    float* dst = out + ((size_t)m * (K >> 4) + (k >> 4)) * 32 + pair16(k & 15);
    dst[0] = h;
    dst[1] = tf32r(v - h);
}

// ---------------------------------------------------------------------------
// tf32 mma.sync GEMM: paired operands, K-chunk 16, TP=48 (conflict-free),
// 2-stage cp.async, 2 CTAs/SM. Block 128x128, 8 warps @ 32(M) x 64(N).
// ---------------------------------------------------------------------------
#define TP   48
#define STGF (256 * TP)                   // floats per stage (A 128 rows + B 128 rows)
#define GEMM_SMEM (2 * STGF * 4)          // 98304 bytes

__global__ __launch_bounds__(256, 2)
void gemm_pair(const float* __restrict__ Ap, const float* __restrict__ Bp,
               float* __restrict__ C, int M, int nch,
               const float* __restrict__ gamma, const float* __restrict__ beta,
               const float* __restrict__ mean,  const float* __restrict__ var)
{
    extern __shared__ float sm[];
    const int tid  = threadIdx.x;
    const int wid  = tid >> 5;
    const int lane = tid & 31;
    const int g    = lane >> 2;
    const int tig  = lane & 3;

    const int n0 = blockIdx.x * 128;
    const int m0 = blockIdx.y * 128;
    const int z  = blockIdx.z;

    const int wm = (wid & 3) * 32;
    const int wn = (wid >> 2) * 64;

    const int K2 = nch * 32;                       // floats per gmem row
    const float* Bb = Bp + (size_t)z * HW * (size_t)K2;
    float*       Cb = C  + (size_t)z * M * HW;

    uint32_t smb;
    asm("{ .reg .u64 t; cvta.to.shared.u64 t, %1; cvt.u32.u64 %0, t; }" : "=r"(smb) : "l"(sm));

    // Fill mapping: thread -> (row = tid>>3 (+32*it), 16B block u = tid&7)
    const int frow = tid >> 3;        // 0..31
    const int u8   = tid & 7;         // 0..7
    const float* gA = Ap + (size_t)(m0 + frow) * K2 + u8 * 4;
    const float* gB = Bb + (size_t)(n0 + frow) * K2 + u8 * 4;
    const uint32_t sA = smb + (uint32_t)(frow * TP + u8 * 4) * 4u;
    const uint32_t sB = sA + (uint32_t)(128 * TP) * 4u;

    float acc[2][8][4];
    #pragma unroll
    for (int mt = 0; mt < 2; mt++)
        #pragma unroll
        for (int nt = 0; nt < 8; nt++)
            #pragma unroll
            for (int j = 0; j < 4; j++) acc[mt][nt][j] = 0.f;

    // prologue: chunk 0 -> stage 0
    #pragma unroll
    for (int it = 0; it < 4; it++) {
        CP_ASYNC16(sA + (uint32_t)(it * 32 * TP) * 4u, gA + (size_t)it * 32 * K2);
        CP_ASYNC16(sB + (uint32_t)(it * 32 * TP) * 4u, gB + (size_t)it * 32 * K2);
    }
    CP_COMMIT();

    for (int c = 0; c < nch; c++) {
        CP_WAIT_ALL();
        __syncthreads();
        if (c + 1 < nch) {
            const uint32_t so = (uint32_t)(((c + 1) & 1)) * (STGF * 4u);
            const int go = (c + 1) * 32;
            #pragma unroll
            for (int it = 0; it < 4; it++) {
                CP_ASYNC16(sA + so + (uint32_t)(it * 32 * TP) * 4u,
                           gA + (size_t)it * 32 * K2 + go);
                CP_ASYNC16(sB + so + (uint32_t)(it * 32 * TP) * 4u,
                           gB + (size_t)it * 32 * K2 + go);
            }
            CP_COMMIT();
        }
        const float* As_ = sm + (c & 1) * STGF;
        const float* Bs_ = As_ + 128 * TP;

        #pragma unroll
        for (int ks = 0; ks < 2; ks++) {
            const int col = ks * 16 + tig * 4;
            float4 r1 = *(const float4*)(As_ + (wm + g     ) * TP + col);
            float4 r2 = *(const float4*)(As_ + (wm + 8  + g) * TP + col);
            float4 r3 = *(const float4*)(As_ + (wm + 16 + g) * TP + col);
            float4 r4 = *(const float4*)(As_ + (wm + 24 + g) * TP + col);
            uint32_t ahi0[4] = { __float_as_uint(r1.x), __float_as_uint(r2.x),
                                 __float_as_uint(r1.z), __float_as_uint(r2.z) };
            uint32_t alo0[4] = { __float_as_uint(r1.y), __float_as_uint(r2.y),
                                 __float_as_uint(r1.w), __float_as_uint(r2.w) };
            uint32_t ahi1[4] = { __float_as_uint(r3.x), __float_as_uint(r4.x),
                                 __float_as_uint(r3.z), __float_as_uint(r4.z) };
            uint32_t alo1[4] = { __float_as_uint(r3.y), __float_as_uint(r4.y),
                                 __float_as_uint(r3.w), __float_as_uint(r4.w) };
            #pragma unroll
            for (int nt = 0; nt < 8; nt++) {
                float4 rb = *(const float4*)(Bs_ + (wn + nt * 8 + g) * TP + col);
                uint32_t bh[2] = { __float_as_uint(rb.x), __float_as_uint(rb.z) };
                uint32_t bl[2] = { __float_as_uint(rb.y), __float_as_uint(rb.w) };
                mma_tf32(acc[0][nt], alo0, bh);
                mma_tf32(acc[0][nt], ahi0, bl);
                mma_tf32(acc[0][nt], ahi0, bh);
                mma_tf32(acc[1][nt], alo1, bh);
                mma_tf32(acc[1][nt], ahi1, bl);
                mma_tf32(acc[1][nt], ahi1, bh);
            }
        }
    }

    // epilogue
    #pragma unroll
    for (int mt = 0; mt < 2; mt++) {
        const int mA = m0 + wm + mt * 16 + g;
        const int mB = mA + 8;
        float sAa = 1.f, hA = 0.f, sBb = 1.f, hB = 0.f;
        if (gamma) {
            float invA = gamma[mA] * rsqrtf(var[mA] + 1e-5f);
            float invB = gamma[mB] * rsqrtf(var[mB] + 1e-5f);
            sAa = invA; hA = beta[mA] - mean[mA] * invA;
            sBb = invB; hB = beta[mB] - mean[mB] * invB;
        }
        float* rowA = Cb + (size_t)mA * HW + n0 + wn + 2 * tig;
        float* rowB = Cb + (size_t)mB * HW + n0 + wn + 2 * tig;
        #pragma unroll
        for (int nt = 0; nt < 8; nt++) {
            float2 oA, oB;
            oA.x = acc[mt][nt][0] * sAa + hA;
            oA.y = acc[mt][nt][1] * sAa + hA;
            oB.x = acc[mt][nt][2] * sBb + hB;
            oB.y = acc[mt][nt][3] * sBb + hB;
            *(float2*)(rowA + nt * 8) = oA;
            *(float2*)(rowB + nt * 8) = oB;
        }
    }
}

// ---------------------------------------------------------------------------
// Transpose x: [b][k=256][n] -> paired xt [b][n][16][32]
// ---------------------------------------------------------------------------
__global__ __launch_bounds__(256)
void transpose_kernel(const float* __restrict__ in, float* __restrict__ outp)
{
    __shared__ float t[32][33];
    const int b  = blockIdx.z;
    const int n0 = blockIdx.x * 32;
    const int k0 = blockIdx.y * 32;
    const int tx = threadIdx.x & 31;
    const int ty = threadIdx.x >> 5;

    const float* ib = in + (size_t)b * CIN * HW;
    float* ob = outp + (size_t)b * HW * (2 * CIN);

    #pragma unroll
    for (int i = 0; i < 4; i++) {
        const int k = k0 + ty + i * 8;
        t[ty + i * 8][tx] = ib[(size_t)k * HW + n0 + tx];
    }
    __syncthreads();
    #pragma unroll
    for (int i = 0; i < 4; i++) {
        const int n = n0 + ty + i * 8;
        const int k = k0 + tx;
        const float v = t[tx][ty + i * 8];
        const float h = tf32r(v);
        float* dst = ob + (size_t)n * (2 * CIN) + (k >> 4) * 32 + pair16(k & 15);
        dst[0] = h;
        dst[1] = tf32r(v - h);
    }
}

// ---------------------------------------------------------------------------
// Fused depthwise 3x3 + grouped 1x1
// ---------------------------------------------------------------------------
__global__ __launch_bounds__(256)
void dwpw_kernel(const float* __restrict__ qkv,
                 const float* __restrict__ wdw,
                 const float* __restrict__ wpw,
                 float* __restrict__ agg)
{
    const int strip = blockIdx.x;
    const int gg    = blockIdx.y;
    const int b     = blockIdx.z;
    const int r0    = strip * 16;

    __shared__ float s_in[8][18][68];
    __shared__ float s_wdw[8][9];
    __shared__ float s_wpw[8][8];

    const int tid = threadIdx.x;
    const float* base = qkv + ((size_t)b * OC_QKV + gg * 8) * HW;

    for (int idx = tid; idx < 8 * 18 * 16; idx += 256) {
        const int seg = idx & 15;
        const int row = idx >> 4;
        const int rr  = row % 18;
        const int ch  = row / 18;
        const int y   = r0 + rr - 1;
        float4 v = make_float4(0.f, 0.f, 0.f, 0.f);
        if (y >= 0 && y < HH)
            v = *(const float4*)(base + (size_t)ch * HW + y * WW + seg * 4);
        float* d = &s_in[ch][rr][1 + seg * 4];
        d[0] = v.x; d[1] = v.y; d[2] = v.z; d[3] = v.w;
        if (seg == 0)  s_in[ch][rr][0]  = 0.f;
        if (seg == 15) s_in[ch][rr][65] = 0.f;
    }
    if (tid < 72)
        s_wdw[tid / 9][tid % 9] = wdw[(size_t)(gg * 8 + tid / 9) * 9 + tid % 9];
    if (tid >= 128 && tid < 192) {
        int t = tid - 128;
        s_wpw[t >> 3][t & 7] = wpw[(size_t)(gg * 8 + (t >> 3)) * 8 + (t & 7)];
    }
    __syncthreads();

    float* obase = agg + ((size_t)b * OC_QKV + gg * 8) * HW + r0 * WW;
    for (int p = tid; p < 16 * WW; p += 256) {
        const int py = p >> 6;
        const int px = p & 63;
        float dwv[8];
        #pragma unroll
        for (int ic = 0; ic < 8; ic++) {
            float s = 0.f;
            #pragma unroll
            for (int ky = 0; ky < 3; ky++)
                #pragma unroll
                for (int kx = 0; kx < 3; kx++)
                    s += s_in[ic][py + ky][px + kx] * s_wdw[ic][ky * 3 + kx];
            dwv[ic] = s;
        }
        #pragma unroll
        for (int oc = 0; oc < 8; oc++) {
            float s = 0.f;
            #pragma unroll
            for (int ic = 0; ic < 8; ic++) s += s_wpw[oc][ic] * dwv[ic];
            obase[(size_t)oc * HW + p] = s;
        }
    }
}

// ---------------------------------------------------------------------------
// kv partial reduction over 4 n-segments
// ---------------------------------------------------------------------------
__global__ __launch_bounds__(256)
void kv_kernel(const float* __restrict__ qkv, const float* __restrict__ agg,
               float* __restrict__ kvout)
{
    const int h   = blockIdx.x;
    const int b   = blockIdx.y;
    const int seg = blockIdx.z;
    const float* src = (h < 32) ? qkv : agg;
    const int ch0 = (h & 31) * 24;
    const float* base = src + ((size_t)b * OC_QKV + ch0) * HW;

    float acc[8][9];
    #pragma unroll
    for (int d = 0; d < 8; d++)
        #pragma unroll
        for (int e = 0; e < 9; e++) acc[d][e] = 0.f;

    const int nend = (seg + 1) * 1024;
    for (int n = seg * 1024 + threadIdx.x; n < nend; n += 256) {
        float kk[8], vv[8];
        #pragma unroll
        for (int d = 0; d < 8; d++)
            kk[d] = fmaxf(base[(size_t)(8 + d) * HW + n], 0.f);
        #pragma unroll
        for (int e = 0; e < 8; e++)
            vv[e] = base[(size_t)(16 + e) * HW + n];
        #pragma unroll
        for (int d = 0; d < 8; d++) {
            #pragma unroll
            for (int e = 0; e < 8; e++) acc[d][e] += kk[d] * vv[e];
            acc[d][8] += kk[d];
        }
    }

    __shared__ float sred[8][72];
    const int lane = threadIdx.x & 31;
    const int warp = threadIdx.x >> 5;
    #pragma unroll
    for (int d = 0; d < 8; d++)
        #pragma unroll
        for (int e = 0; e < 9; e++) {
            float v = acc[d][e];
            #pragma unroll
            for (int o = 16; o > 0; o >>= 1)
                v += __shfl_down_sync(0xffffffffu, v, o);
            if (lane == 0) sred[warp][d * 9 + e] = v;
        }
    __syncthreads();
    if (threadIdx.x < 72) {
        float s = 0.f;
        #pragma unroll
        for (int w = 0; w < 8; w++) s += sred[w][threadIdx.x];
        kvout[(((size_t)b * HEADS + h) * 4 + seg) * 72 + threadIdx.x] = s;
    }
}

// ---------------------------------------------------------------------------
// attention apply -> paired att [b][n][32][32]
// head h occupies chunk h>>1, half (h&1)*16
// ---------------------------------------------------------------------------
__global__ __launch_bounds__(256)
void apply_kernel(const float* __restrict__ qkv, const float* __restrict__ agg,
                  const float* __restrict__ kvin, float* __restrict__ attp)
{
    const int h = blockIdx.x;
    const int b = blockIdx.y;
    const float* src = (h < 32) ? qkv : agg;
    const int ch0 = (h & 31) * 24;
    const float* qb = src + ((size_t)b * OC_QKV + ch0) * HW;

    __shared__ float s_kv[72];
    if (threadIdx.x < 72) {
        const float* kp = kvin + ((size_t)b * HEADS + h) * 4 * 72 + threadIdx.x;
        s_kv[threadIdx.x] = kp[0] + kp[72] + kp[144] + kp[216];
    }
    __syncthreads();

    float* ob = attp + (size_t)b * HW * (2 * ATT_CH) + (h >> 1) * 32 + (h & 1) * 16;
    for (int n = threadIdx.x; n < HW; n += 256) {
        float q[8];
        #pragma unroll
        for (int d = 0; d < 8; d++)
            q[d] = fmaxf(qb[(size_t)d * HW + n], 0.f);
        float num[9];
        #pragma unroll
        for (int e = 0; e < 9; e++) {
            float s = 0.f;
            #pragma unroll
            for (int d = 0; d < 8; d++) s += q[d] * s_kv[d * 9 + e];
            num[e] = s;
        }
        const float r = 1.0f / (num[8] + 1e-15f);
        float hv[8], lv[8];
        #pragma unroll
        for (int d = 0; d < 8; d++) {
            const float v = num[d] * r;
            hv[d] = tf32r(v);
            lv[d] = tf32r(v - hv[d]);
        }
        float* dst = ob + (size_t)n * (2 * ATT_CH);
        *(float4*)(dst + 0)  = make_float4(hv[0], lv[0], hv[4], lv[4]);
        *(float4*)(dst + 4)  = make_float4(hv[1], lv[1], hv[5], lv[5]);
        *(float4*)(dst + 8)  = make_float4(hv[2], lv[2], hv[6], lv[6]);
        *(float4*)(dst + 12) = make_float4(hv[3], lv[3], hv[7], lv[7]);
    }
}

// ---------------------------------------------------------------------------
// Launch
// ---------------------------------------------------------------------------
extern "C" void kernel_launch(void* const* d_in, const int* in_sizes, int n_in,
                              void* d_out, int out_size)
{
    const float* x      = (const float*)d_in[0];
    const float* w_qkv  = (const float*)d_in[1];
    const float* w_dw   = (const float*)d_in[2];
    const float* w_pw   = (const float*)d_in[3];
    const float* w_proj = (const float*)d_in[4];
    const float* gamma  = (const float*)d_in[5];
    const float* beta   = (const float*)d_in[6];
    const float* mean   = (const float*)d_in[7];
    const float* var    = (const float*)d_in[8];
    float* out = (float*)d_out;

    float *qkv_p, *agg_p, *kv_p, *attp_p, *xtp_p, *wqp_p, *wpp_p;
    cudaGetSymbolAddress((void**)&qkv_p,  g_qkv);
    cudaGetSymbolAddress((void**)&agg_p,  g_agg);
    cudaGetSymbolAddress((void**)&kv_p,   g_kv);
    cudaGetSymbolAddress((void**)&attp_p, g_attp);
    cudaGetSymbolAddress((void**)&xtp_p,  g_xtp);
    cudaGetSymbolAddress((void**)&wqp_p,  g_wqp);
    cudaGetSymbolAddress((void**)&wpp_p,  g_wpp);

    cudaFuncSetAttribute(gemm_pair, cudaFuncAttributeMaxDynamicSharedMemorySize, GEMM_SMEM);

    split_kernel<<<(OC_QKV * CIN + 255) / 256, 256>>>(w_qkv, wqp_p, OC_QKV, CIN);
    split_kernel<<<(OC_OUT * K_PROJ + 255) / 256, 256>>>(w_proj, wpp_p, OC_OUT, K_PROJ);
    {
        dim3 grid(HW / 32, CIN / 32, BATCH);
        transpose_kernel<<<grid, 256>>>(x, xtp_p);
    }
    // 1) qkv = W_qkv * x : M=768, nch=16
    {
        dim3 grid(HW / 128, OC_QKV / 128, BATCH);
        gemm_pair<<<grid, 256, GEMM_SMEM>>>(wqp_p, xtp_p, qkv_p, OC_QKV, CIN / 16,
                                            nullptr, nullptr, nullptr, nullptr);
    }
    // 2) depthwise + grouped pointwise
    {
        dim3 grid(4, 96, BATCH);
        dwpw_kernel<<<grid, 256>>>(qkv_p, w_dw, w_pw, agg_p);
    }
    // 3) kv partial reduction
    {
        dim3 grid(HEADS, BATCH, 4);
        kv_kernel<<<grid, 256>>>(qkv_p, agg_p, kv_p);
    }
    // 4) attention apply
    {
        dim3 grid(HEADS, BATCH);
        apply_kernel<<<grid, 256>>>(qkv_p, agg_p, kv_p, attp_p);
    }
    // 5) y = W_proj * att + BN : M=256, nch=32
    {
        dim3 grid(HW / 128, OC_OUT / 128, BATCH);
        gemm_pair<<<grid, 256, GEMM_SMEM>>>(wpp_p, attp_p, out, OC_OUT, K_PROJ / 16,
                                            gamma, beta, mean, var);
    }
}

// round 9
// speedup vs baseline: 1.4069x; 1.0684x over previous
#include <cuda_runtime.h>
#include <cstdint>
#include <cstddef>

// Problem constants
#define BATCH   16
#define CIN     256
#define HH      64
#define WW      64
#define HW      4096
#define OC_QKV  768
#define HEADS   64
#define ATT_CH  512
#define OC_OUT  256
#define K_PROJ  512

// ---------------------------------------------------------------------------
// Paired layout, 16-k chunks: per row, per chunk, 32 floats:
//   off(kk) = (kk/8)*16 + (kk%4)*4 + ((kk%8)/4)*2 ; hi at off, lo at off+1
// ---------------------------------------------------------------------------
__device__ float g_qkv [(size_t)BATCH * OC_QKV * HW];
__device__ float g_agg [(size_t)BATCH * OC_QKV * HW];
__device__ float g_kv  [(size_t)BATCH * HEADS * 4 * 72];
__device__ float g_attp[(size_t)BATCH * HW * 2 * ATT_CH]; // [b][n][32ch][32]
__device__ float g_xtp [(size_t)BATCH * HW * 2 * CIN];    // [b][n][16ch][32]
__device__ float g_wqp [(size_t)OC_QKV * 2 * CIN];
__device__ float g_wpp [(size_t)OC_OUT * 2 * K_PROJ];

// ---------------------------------------------------------------------------
// Helpers
// ---------------------------------------------------------------------------
__device__ __forceinline__ float tf32r(float x) {
    float r;
    asm("cvt.rna.tf32.f32 %0, %1;" : "=f"(r) : "f"(x));
    return r;
}
__device__ __forceinline__ int pair16(int kk) {   // kk in 0..15
    return ((kk >> 3) << 4) + ((kk & 3) << 2) + (((kk >> 2) & 1) << 1);
}
__device__ __forceinline__ void mma_tf32(float* d, const uint32_t* a, const uint32_t* b) {
    asm volatile(
        "mma.sync.aligned.m16n8k8.row.col.f32.tf32.tf32.f32 "
        "{%0,%1,%2,%3}, {%4,%5,%6,%7}, {%8,%9}, {%0,%1,%2,%3};"
        : "+f"(d[0]), "+f"(d[1]), "+f"(d[2]), "+f"(d[3])
        : "r"(a[0]), "r"(a[1]), "r"(a[2]), "r"(a[3]), "r"(b[0]), "r"(b[1]));
}
#define CP_ASYNC16(sa, gp) \
    asm volatile("cp.async.ca.shared.global [%0], [%1], 16;" :: "r"(sa), "l"(gp))
#define CP_COMMIT() asm volatile("cp.async.commit_group;")
#define CP_WAIT_ALL() asm volatile("cp.async.wait_group 0;")

// ---------------------------------------------------------------------------
// Weight splitter -> paired layout [m][K/16][32]
// ---------------------------------------------------------------------------
__global__ __launch_bounds__(256)
void split_kernel(const float* __restrict__ in, float* __restrict__ out, int M, int K)
{
    const int i = blockIdx.x * 256 + threadIdx.x;
    if (i >= M * K) return;
    const int m = i / K;
    const int k = i - m * K;
    const float v = in[i];
    const float h = tf32r(v);
    float* dst = out + ((size_t)m * (K >> 4) + (k >> 4)) * 32 + pair16(k & 15);
    dst[0] = h;
    dst[1] = tf32r(v - h);
}

// ---------------------------------------------------------------------------
// tf32 mma.sync GEMM: paired operands, K-chunk 16, TP=48, 2-stage cp.async,
// 2 CTAs/SM. NCH compile-time -> constant addressing; TERMS = split terms.
// Block 128x128, 8 warps @ 32(M) x 64(N).
// ---------------------------------------------------------------------------
#define TP   48
#define STGF (256 * TP)                   // floats per stage
#define GEMM_SMEM (2 * STGF * 4)          // 98304 bytes

template<int NCH, int TERMS>
__global__ __launch_bounds__(256, 2)
void gemm_pair(const float* __restrict__ Ap, const float* __restrict__ Bp,
               float* __restrict__ C, int M,
               const float* __restrict__ gamma, const float* __restrict__ beta,
               const float* __restrict__ mean,  const float* __restrict__ var)
{
    extern __shared__ float sm[];
    const int tid  = threadIdx.x;
    const int wid  = tid >> 5;
    const int lane = tid & 31;
    const int g    = lane >> 2;
    const int tig  = lane & 3;

    const int n0 = blockIdx.x * 128;
    const int m0 = blockIdx.y * 128;
    const int z  = blockIdx.z;

    const int wm = (wid & 3) * 32;
    const int wn = (wid >> 2) * 64;

    constexpr int K2 = NCH * 32;                   // floats per gmem row
    const float* Bb = Bp + (size_t)z * HW * (size_t)K2;
    float*       Cb = C  + (size_t)z * M * HW;

    uint32_t smb;
    asm("{ .reg .u64 t; cvta.to.shared.u64 t, %1; cvt.u32.u64 %0, t; }" : "=r"(smb) : "l"(sm));

    // Fill mapping: thread -> (row = tid>>3 (+32*it), 16B block u = tid&7)
    const int frow = tid >> 3;        // 0..31
    const int u8   = tid & 7;         // 0..7
    const float* gA = Ap + (size_t)(m0 + frow) * K2 + u8 * 4;
    const float* gB = Bb + (size_t)(n0 + frow) * K2 + u8 * 4;
    const uint32_t sA = smb + (uint32_t)(frow * TP + u8 * 4) * 4u;
    const uint32_t sB = sA + (uint32_t)(128 * TP) * 4u;

    float acc[2][8][4];
    #pragma unroll
    for (int mt = 0; mt < 2; mt++)
        #pragma unroll
        for (int nt = 0; nt < 8; nt++)
            #pragma unroll
            for (int j = 0; j < 4; j++) acc[mt][nt][j] = 0.f;

    // prologue: chunk 0 -> stage 0
    #pragma unroll
    for (int it = 0; it < 4; it++) {
        CP_ASYNC16(sA + (uint32_t)(it * 32 * TP) * 4u, gA + (size_t)it * 32 * K2);
        CP_ASYNC16(sB + (uint32_t)(it * 32 * TP) * 4u, gB + (size_t)it * 32 * K2);
    }
    CP_COMMIT();

    #pragma unroll 2
    for (int c = 0; c < NCH; c++) {
        CP_WAIT_ALL();
        __syncthreads();
        if (c + 1 < NCH) {
            const uint32_t so = (uint32_t)(((c + 1) & 1)) * (STGF * 4u);
            const int go = (c + 1) * 32;
            #pragma unroll
            for (int it = 0; it < 4; it++) {
                CP_ASYNC16(sA + so + (uint32_t)(it * 32 * TP) * 4u,
                           gA + (size_t)it * 32 * K2 + go);
                CP_ASYNC16(sB + so + (uint32_t)(it * 32 * TP) * 4u,
                           gB + (size_t)it * 32 * K2 + go);
            }
            CP_COMMIT();
        }
        const float* As_ = sm + (c & 1) * STGF;
        const float* Bs_ = As_ + 128 * TP;

        #pragma unroll
        for (int ks = 0; ks < 2; ks++) {
            const int col = ks * 16 + tig * 4;
            float4 r1 = *(const float4*)(As_ + (wm + g     ) * TP + col);
            float4 r2 = *(const float4*)(As_ + (wm + 8  + g) * TP + col);
            float4 r3 = *(const float4*)(As_ + (wm + 16 + g) * TP + col);
            float4 r4 = *(const float4*)(As_ + (wm + 24 + g) * TP + col);
            uint32_t ahi0[4] = { __float_as_uint(r1.x), __float_as_uint(r2.x),
                                 __float_as_uint(r1.z), __float_as_uint(r2.z) };
            uint32_t alo0[4] = { __float_as_uint(r1.y), __float_as_uint(r2.y),
                                 __float_as_uint(r1.w), __float_as_uint(r2.w) };
            uint32_t ahi1[4] = { __float_as_uint(r3.x), __float_as_uint(r4.x),
                                 __float_as_uint(r3.z), __float_as_uint(r4.z) };
            uint32_t alo1[4] = { __float_as_uint(r3.y), __float_as_uint(r4.y),
                                 __float_as_uint(r3.w), __float_as_uint(r4.w) };
            #pragma unroll
            for (int nt = 0; nt < 8; nt++) {
                float4 rb = *(const float4*)(Bs_ + (wn + nt * 8 + g) * TP + col);
                uint32_t bh[2] = { __float_as_uint(rb.x), __float_as_uint(rb.z) };
                mma_tf32(acc[0][nt], alo0, bh);
                mma_tf32(acc[1][nt], alo1, bh);
                if (TERMS == 3) {
                    uint32_t bl[2] = { __float_as_uint(rb.y), __float_as_uint(rb.w) };
                    mma_tf32(acc[0][nt], ahi0, bl);
                    mma_tf32(acc[1][nt], ahi1, bl);
                }
                mma_tf32(acc[0][nt], ahi0, bh);
                mma_tf32(acc[1][nt], ahi1, bh);
            }
        }
    }

    // epilogue
    #pragma unroll
    for (int mt = 0; mt < 2; mt++) {
        const int mA = m0 + wm + mt * 16 + g;
        const int mB = mA + 8;
        float sAa = 1.f, hA = 0.f, sBb = 1.f, hB = 0.f;
        if (gamma) {
            float invA = gamma[mA] * rsqrtf(var[mA] + 1e-5f);
            float invB = gamma[mB] * rsqrtf(var[mB] + 1e-5f);
            sAa = invA; hA = beta[mA] - mean[mA] * invA;
            sBb = invB; hB = beta[mB] - mean[mB] * invB;
        }
        float* rowA = Cb + (size_t)mA * HW + n0 + wn + 2 * tig;
        float* rowB = Cb + (size_t)mB * HW + n0 + wn + 2 * tig;
        #pragma unroll
        for (int nt = 0; nt < 8; nt++) {
            float2 oA, oB;
            oA.x = acc[mt][nt][0] * sAa + hA;
            oA.y = acc[mt][nt][1] * sAa + hA;
            oB.x = acc[mt][nt][2] * sBb + hB;
            oB.y = acc[mt][nt][3] * sBb + hB;
            *(float2*)(rowA + nt * 8) = oA;
            *(float2*)(rowB + nt * 8) = oB;
        }
    }
}

// ---------------------------------------------------------------------------
// Transpose x: [b][k=256][n] -> paired xt [b][n][16][32]
// ---------------------------------------------------------------------------
__global__ __launch_bounds__(256)
void transpose_kernel(const float* __restrict__ in, float* __restrict__ outp)
{
    __shared__ float t[32][33];
    const int b  = blockIdx.z;
    const int n0 = blockIdx.x * 32;
    const int k0 = blockIdx.y * 32;
    const int tx = threadIdx.x & 31;
    const int ty = threadIdx.x >> 5;

    const float* ib = in + (size_t)b * CIN * HW;
    float* ob = outp + (size_t)b * HW * (2 * CIN);

    #pragma unroll
    for (int i = 0; i < 4; i++) {
        const int k = k0 + ty + i * 8;
        t[ty + i * 8][tx] = ib[(size_t)k * HW + n0 + tx];
    }
    __syncthreads();
    #pragma unroll
    for (int i = 0; i < 4; i++) {
        const int n = n0 + ty + i * 8;
        const int k = k0 + tx;
        const float v = t[tx][ty + i * 8];
        const float h = tf32r(v);
        float* dst = ob + (size_t)n * (2 * CIN) + (k >> 4) * 32 + pair16(k & 15);
        dst[0] = h;
        dst[1] = tf32r(v - h);
    }
}

// ---------------------------------------------------------------------------
// Fused depthwise 3x3 + grouped 1x1
// ---------------------------------------------------------------------------
__global__ __launch_bounds__(256)
void dwpw_kernel(const float* __restrict__ qkv,
                 const float* __restrict__ wdw,
                 const float* __restrict__ wpw,
                 float* __restrict__ agg)
{
    const int strip = blockIdx.x;
    const int gg    = blockIdx.y;
    const int b     = blockIdx.z;
    const int r0    = strip * 16;

    __shared__ float s_in[8][18][68];
    __shared__ float s_wdw[8][9];
    __shared__ float s_wpw[8][8];

    const int tid = threadIdx.x;
    const float* base = qkv + ((size_t)b * OC_QKV + gg * 8) * HW;

    for (int idx = tid; idx < 8 * 18 * 16; idx += 256) {
        const int seg = idx & 15;
        const int row = idx >> 4;
        const int rr  = row % 18;
        const int ch  = row / 18;
        const int y   = r0 + rr - 1;
        float4 v = make_float4(0.f, 0.f, 0.f, 0.f);
        if (y >= 0 && y < HH)
            v = *(const float4*)(base + (size_t)ch * HW + y * WW + seg * 4);
        float* d = &s_in[ch][rr][1 + seg * 4];
        d[0] = v.x; d[1] = v.y; d[2] = v.z; d[3] = v.w;
        if (seg == 0)  s_in[ch][rr][0]  = 0.f;
        if (seg == 15) s_in[ch][rr][65] = 0.f;
    }
    if (tid < 72)
        s_wdw[tid / 9][tid % 9] = wdw[(size_t)(gg * 8 + tid / 9) * 9 + tid % 9];
    if (tid >= 128 && tid < 192) {
        int t = tid - 128;
        s_wpw[t >> 3][t & 7] = wpw[(size_t)(gg * 8 + (t >> 3)) * 8 + (t & 7)];
    }
    __syncthreads();

    float* obase = agg + ((size_t)b * OC_QKV + gg * 8) * HW + r0 * WW;
    for (int p = tid; p < 16 * WW; p += 256) {
        const int py = p >> 6;
        const int px = p & 63;
        float dwv[8];
        #pragma unroll
        for (int ic = 0; ic < 8; ic++) {
            float s = 0.f;
            #pragma unroll
            for (int ky = 0; ky < 3; ky++)
                #pragma unroll
                for (int kx = 0; kx < 3; kx++)
                    s += s_in[ic][py + ky][px + kx] * s_wdw[ic][ky * 3 + kx];
            dwv[ic] = s;
        }
        #pragma unroll
        for (int oc = 0; oc < 8; oc++) {
            float s = 0.f;
            #pragma unroll
            for (int ic = 0; ic < 8; ic++) s += s_wpw[oc][ic] * dwv[ic];
            obase[(size_t)oc * HW + p] = s;
        }
    }
}

// ---------------------------------------------------------------------------
// kv partial reduction over 4 n-segments
// ---------------------------------------------------------------------------
__global__ __launch_bounds__(256)
void kv_kernel(const float* __restrict__ qkv, const float* __restrict__ agg,
               float* __restrict__ kvout)
{
    const int h   = blockIdx.x;
    const int b   = blockIdx.y;
    const int seg = blockIdx.z;
    const float* src = (h < 32) ? qkv : agg;
    const int ch0 = (h & 31) * 24;
    const float* base = src + ((size_t)b * OC_QKV + ch0) * HW;

    float acc[8][9];
    #pragma unroll
    for (int d = 0; d < 8; d++)
        #pragma unroll
        for (int e = 0; e < 9; e++) acc[d][e] = 0.f;

    const int nend = (seg + 1) * 1024;
    for (int n = seg * 1024 + threadIdx.x; n < nend; n += 256) {
        float kk[8], vv[8];
        #pragma unroll
        for (int d = 0; d < 8; d++)
            kk[d] = fmaxf(base[(size_t)(8 + d) * HW + n], 0.f);
        #pragma unroll
        for (int e = 0; e < 8; e++)
            vv[e] = base[(size_t)(16 + e) * HW + n];
        #pragma unroll
        for (int d = 0; d < 8; d++) {
            #pragma unroll
            for (int e = 0; e < 8; e++) acc[d][e] += kk[d] * vv[e];
            acc[d][8] += kk[d];
        }
    }

    __shared__ float sred[8][72];
    const int lane = threadIdx.x & 31;
    const int warp = threadIdx.x >> 5;
    #pragma unroll
    for (int d = 0; d < 8; d++)
        #pragma unroll
        for (int e = 0; e < 9; e++) {
            float v = acc[d][e];
            #pragma unroll
            for (int o = 16; o > 0; o >>= 1)
                v += __shfl_down_sync(0xffffffffu, v, o);
            if (lane == 0) sred[warp][d * 9 + e] = v;
        }
    __syncthreads();
    if (threadIdx.x < 72) {
        float s = 0.f;
        #pragma unroll
        for (int w = 0; w < 8; w++) s += sred[w][threadIdx.x];
        kvout[(((size_t)b * HEADS + h) * 4 + seg) * 72 + threadIdx.x] = s;
    }
}

// ---------------------------------------------------------------------------
// attention apply -> paired att [b][n][32][32]
// head h occupies chunk h>>1, half (h&1)*16
// ---------------------------------------------------------------------------
__global__ __launch_bounds__(256)
void apply_kernel(const float* __restrict__ qkv, const float* __restrict__ agg,
                  const float* __restrict__ kvin, float* __restrict__ attp)
{
    const int h = blockIdx.x;
    const int b = blockIdx.y;
    const float* src = (h < 32) ? qkv : agg;
    const int ch0 = (h & 31) * 24;
    const float* qb = src + ((size_t)b * OC_QKV + ch0) * HW;

    __shared__ float s_kv[72];
    if (threadIdx.x < 72) {
        const float* kp = kvin + ((size_t)b * HEADS + h) * 4 * 72 + threadIdx.x;
        s_kv[threadIdx.x] = kp[0] + kp[72] + kp[144] + kp[216];
    }
    __syncthreads();

    float* ob = attp + (size_t)b * HW * (2 * ATT_CH) + (h >> 1) * 32 + (h & 1) * 16;
    for (int n = threadIdx.x; n < HW; n += 256) {
        float q[8];
        #pragma unroll
        for (int d = 0; d < 8; d++)
            q[d] = fmaxf(qb[(size_t)d * HW + n], 0.f);
        float num[9];
        #pragma unroll
        for (int e = 0; e < 9; e++) {
            float s = 0.f;
            #pragma unroll
            for (int d = 0; d < 8; d++) s += q[d] * s_kv[d * 9 + e];
            num[e] = s;
        }
        const float r = 1.0f / (num[8] + 1e-15f);
        float hv[8], lv[8];
        #pragma unroll
        for (int d = 0; d < 8; d++) {
            const float v = num[d] * r;
            hv[d] = tf32r(v);
            lv[d] = tf32r(v - hv[d]);
        }
        float* dst = ob + (size_t)n * (2 * ATT_CH);
        *(float4*)(dst + 0)  = make_float4(hv[0], lv[0], hv[4], lv[4]);
        *(float4*)(dst + 4)  = make_float4(hv[1], lv[1], hv[5], lv[5]);
        *(float4*)(dst + 8)  = make_float4(hv[2], lv[2], hv[6], lv[6]);
        *(float4*)(dst + 12) = make_float4(hv[3], lv[3], hv[7], lv[7]);
    }
}

// ---------------------------------------------------------------------------
// Launch
// ---------------------------------------------------------------------------
extern "C" void kernel_launch(void* const* d_in, const int* in_sizes, int n_in,
                              void* d_out, int out_size)
{
    const float* x      = (const float*)d_in[0];
    const float* w_qkv  = (const float*)d_in[1];
    const float* w_dw   = (const float*)d_in[2];
    const float* w_pw   = (const float*)d_in[3];
    const float* w_proj = (const float*)d_in[4];
    const float* gamma  = (const float*)d_in[5];
    const float* beta   = (const float*)d_in[6];
    const float* mean   = (const float*)d_in[7];
    const float* var    = (const float*)d_in[8];
    float* out = (float*)d_out;

    float *qkv_p, *agg_p, *kv_p, *attp_p, *xtp_p, *wqp_p, *wpp_p;
    cudaGetSymbolAddress((void**)&qkv_p,  g_qkv);
    cudaGetSymbolAddress((void**)&agg_p,  g_agg);
    cudaGetSymbolAddress((void**)&kv_p,   g_kv);
    cudaGetSymbolAddress((void**)&attp_p, g_attp);
    cudaGetSymbolAddress((void**)&xtp_p,  g_xtp);
    cudaGetSymbolAddress((void**)&wqp_p,  g_wqp);
    cudaGetSymbolAddress((void**)&wpp_p,  g_wpp);

    cudaFuncSetAttribute(gemm_pair<16, 3>, cudaFuncAttributeMaxDynamicSharedMemorySize, GEMM_SMEM);
    cudaFuncSetAttribute(gemm_pair<32, 2>, cudaFuncAttributeMaxDynamicSharedMemorySize, GEMM_SMEM);

    split_kernel<<<(OC_QKV * CIN + 255) / 256, 256>>>(w_qkv, wqp_p, OC_QKV, CIN);
    split_kernel<<<(OC_OUT * K_PROJ + 255) / 256, 256>>>(w_proj, wpp_p, OC_OUT, K_PROJ);
    {
        dim3 grid(HW / 32, CIN / 32, BATCH);
        transpose_kernel<<<grid, 256>>>(x, xtp_p);
    }
    // 1) qkv = W_qkv * x : M=768, NCH=16, 3-term (feeds amplifying chain)
    {
        dim3 grid(HW / 128, OC_QKV / 128, BATCH);
        gemm_pair<16, 3><<<grid, 256, GEMM_SMEM>>>(wqp_p, xtp_p, qkv_p, OC_QKV,
                                                   nullptr, nullptr, nullptr, nullptr);
    }
    // 2) depthwise + grouped pointwise
    {
        dim3 grid(4, 96, BATCH);
        dwpw_kernel<<<grid, 256>>>(qkv_p, w_dw, w_pw, agg_p);
    }
    // 3) kv partial reduction
    {
        dim3 grid(HEADS, BATCH, 4);
        kv_kernel<<<grid, 256>>>(qkv_p, agg_p, kv_p);
    }
    // 4) attention apply
    {
        dim3 grid(HEADS, BATCH);
        apply_kernel<<<grid, 256>>>(qkv_p, agg_p, kv_p, attp_p);
    }
    // 5) y = W_proj * att + BN : M=256, NCH=32, 2-term (terminal, unamplified)
    {
        dim3 grid(HW / 128, OC_OUT / 128, BATCH);
        gemm_pair<32, 2><<<grid, 256, GEMM_SMEM>>>(wpp_p, attp_p, out, OC_OUT,
                                                   gamma, beta, mean, var);
    }
}

// round 10
// speedup vs baseline: 1.4636x; 1.0403x over previous
#include <cuda_runtime.h>
#include <cstdint>
#include <cstddef>

// Problem constants
#define BATCH   16
#define CIN     256
#define HH      64
#define WW      64
#define HW      4096
#define OC_QKV  768
#define HEADS   64
#define ATT_CH  512
#define OC_OUT  256
#define K_PROJ  512

// ---------------------------------------------------------------------------
// Paired layout (A operands + GEMM1 B), 16-k chunks, 32 floats/chunk:
//   off(kk) = (kk/8)*16 + (kk%4)*4 + ((kk%8)/4)*2 ; hi at off, lo at off+1
// Hi-only layout (GEMM2 B), 16 floats/chunk:
//   off(kk) = (kk/8)*8 + (kk%4)*2 + ((kk%8)/4)
// ---------------------------------------------------------------------------
__device__ float g_qkv [(size_t)BATCH * OC_QKV * HW];
__device__ float g_agg [(size_t)BATCH * OC_QKV * HW];
__device__ float g_kv  [(size_t)BATCH * HEADS * 4 * 72];
__device__ float g_attp[(size_t)BATCH * HW * ATT_CH];    // hi-only [b][n][512]
__device__ float g_xtp [(size_t)BATCH * HW * 2 * CIN];   // paired  [b][n][16][32]
__device__ float g_wqp [(size_t)OC_QKV * 2 * CIN];
__device__ float g_wpp [(size_t)OC_OUT * 2 * K_PROJ];

// ---------------------------------------------------------------------------
// Helpers
// ---------------------------------------------------------------------------
__device__ __forceinline__ float tf32r(float x) {
    float r;
    asm("cvt.rna.tf32.f32 %0, %1;" : "=f"(r) : "f"(x));
    return r;
}
__device__ __forceinline__ int pair16(int kk) {
    return ((kk >> 3) << 4) + ((kk & 3) << 2) + (((kk >> 2) & 1) << 1);
}
__device__ __forceinline__ void mma_tf32(float* d, const uint32_t* a, const uint32_t* b) {
    asm volatile(
        "mma.sync.aligned.m16n8k8.row.col.f32.tf32.tf32.f32 "
        "{%0,%1,%2,%3}, {%4,%5,%6,%7}, {%8,%9}, {%0,%1,%2,%3};"
        : "+f"(d[0]), "+f"(d[1]), "+f"(d[2]), "+f"(d[3])
        : "r"(a[0]), "r"(a[1]), "r"(a[2]), "r"(a[3]), "r"(b[0]), "r"(b[1]));
}
#define CP_ASYNC16(sa, gp) \
    asm volatile("cp.async.ca.shared.global [%0], [%1], 16;" :: "r"(sa), "l"(gp))
#define CP_COMMIT() asm volatile("cp.async.commit_group;")
#define CP_WAIT_ALL() asm volatile("cp.async.wait_group 0;")

// ---------------------------------------------------------------------------
// Weight splitter -> paired layout [m][K/16][32]
// ---------------------------------------------------------------------------
__global__ __launch_bounds__(256)
void split_kernel(const float* __restrict__ in, float* __restrict__ out, int M, int K)
{
    const int i = blockIdx.x * 256 + threadIdx.x;
    if (i >= M * K) return;
    const int m = i / K;
    const int k = i - m * K;
    const float v = in[i];
    const float h = tf32r(v);
    float* dst = out + ((size_t)m * (K >> 4) + (k >> 4)) * 32 + pair16(k & 15);
    dst[0] = h;
    dst[1] = tf32r(v - h);
}

// ---------------------------------------------------------------------------
// GEMM1: 3-term split, paired A + paired B. K-chunk 16, TP=48, 2-stage,
// 2 CTAs/SM, block 128x128, 8 warps @ 32(M) x 64(N).  (unchanged from R9)
// ---------------------------------------------------------------------------
#define TP   48
#define STGF (256 * TP)
#define GEMM_SMEM (2 * STGF * 4)          // 98304 bytes

template<int NCH>
__global__ __launch_bounds__(256, 2)
void gemm_pair(const float* __restrict__ Ap, const float* __restrict__ Bp,
               float* __restrict__ C, int M)
{
    extern __shared__ float sm[];
    const int tid  = threadIdx.x;
    const int wid  = tid >> 5;
    const int lane = tid & 31;
    const int g    = lane >> 2;
    const int tig  = lane & 3;

    const int n0 = blockIdx.x * 128;
    const int m0 = blockIdx.y * 128;
    const int z  = blockIdx.z;

    const int wm = (wid & 3) * 32;
    const int wn = (wid >> 2) * 64;

    constexpr int K2 = NCH * 32;
    const float* Bb = Bp + (size_t)z * HW * (size_t)K2;
    float*       Cb = C  + (size_t)z * M * HW;

    uint32_t smb;
    asm("{ .reg .u64 t; cvta.to.shared.u64 t, %1; cvt.u32.u64 %0, t; }" : "=r"(smb) : "l"(sm));

    const int frow = tid >> 3;
    const int u8   = tid & 7;
    const float* gA = Ap + (size_t)(m0 + frow) * K2 + u8 * 4;
    const float* gB = Bb + (size_t)(n0 + frow) * K2 + u8 * 4;
    const uint32_t sA = smb + (uint32_t)(frow * TP + u8 * 4) * 4u;
    const uint32_t sB = sA + (uint32_t)(128 * TP) * 4u;

    float acc[2][8][4];
    #pragma unroll
    for (int mt = 0; mt < 2; mt++)
        #pragma unroll
        for (int nt = 0; nt < 8; nt++)
            #pragma unroll
            for (int j = 0; j < 4; j++) acc[mt][nt][j] = 0.f;

    #pragma unroll
    for (int it = 0; it < 4; it++) {
        CP_ASYNC16(sA + (uint32_t)(it * 32 * TP) * 4u, gA + (size_t)it * 32 * K2);
        CP_ASYNC16(sB + (uint32_t)(it * 32 * TP) * 4u, gB + (size_t)it * 32 * K2);
    }
    CP_COMMIT();

    #pragma unroll 2
    for (int c = 0; c < NCH; c++) {
        CP_WAIT_ALL();
        __syncthreads();
        if (c + 1 < NCH) {
            const uint32_t so = (uint32_t)(((c + 1) & 1)) * (STGF * 4u);
            const int go = (c + 1) * 32;
            #pragma unroll
            for (int it = 0; it < 4; it++) {
                CP_ASYNC16(sA + so + (uint32_t)(it * 32 * TP) * 4u,
                           gA + (size_t)it * 32 * K2 + go);
                CP_ASYNC16(sB + so + (uint32_t)(it * 32 * TP) * 4u,
                           gB + (size_t)it * 32 * K2 + go);
            }
            CP_COMMIT();
        }
        const float* As_ = sm + (c & 1) * STGF;
        const float* Bs_ = As_ + 128 * TP;

        #pragma unroll
        for (int ks = 0; ks < 2; ks++) {
            const int col = ks * 16 + tig * 4;
            float4 r1 = *(const float4*)(As_ + (wm + g     ) * TP + col);
            float4 r2 = *(const float4*)(As_ + (wm + 8  + g) * TP + col);
            float4 r3 = *(const float4*)(As_ + (wm + 16 + g) * TP + col);
            float4 r4 = *(const float4*)(As_ + (wm + 24 + g) * TP + col);
            uint32_t ahi0[4] = { __float_as_uint(r1.x), __float_as_uint(r2.x),
                                 __float_as_uint(r1.z), __float_as_uint(r2.z) };
            uint32_t alo0[4] = { __float_as_uint(r1.y), __float_as_uint(r2.y),
                                 __float_as_uint(r1.w), __float_as_uint(r2.w) };
            uint32_t ahi1[4] = { __float_as_uint(r3.x), __float_as_uint(r4.x),
                                 __float_as_uint(r3.z), __float_as_uint(r4.z) };
            uint32_t alo1[4] = { __float_as_uint(r3.y), __float_as_uint(r4.y),
                                 __float_as_uint(r3.w), __float_as_uint(r4.w) };
            #pragma unroll
            for (int nt = 0; nt < 8; nt++) {
                float4 rb = *(const float4*)(Bs_ + (wn + nt * 8 + g) * TP + col);
                uint32_t bh[2] = { __float_as_uint(rb.x), __float_as_uint(rb.z) };
                uint32_t bl[2] = { __float_as_uint(rb.y), __float_as_uint(rb.w) };
                mma_tf32(acc[0][nt], alo0, bh);
                mma_tf32(acc[1][nt], alo1, bh);
                mma_tf32(acc[0][nt], ahi0, bl);
                mma_tf32(acc[1][nt], ahi1, bl);
                mma_tf32(acc[0][nt], ahi0, bh);
                mma_tf32(acc[1][nt], ahi1, bh);
            }
        }
    }

    #pragma unroll
    for (int mt = 0; mt < 2; mt++) {
        const int mA = m0 + wm + mt * 16 + g;
        const int mB = mA + 8;
        float* rowA = Cb + (size_t)mA * HW + n0 + wn + 2 * tig;
        float* rowB = Cb + (size_t)mB * HW + n0 + wn + 2 * tig;
        #pragma unroll
        for (int nt = 0; nt < 8; nt++) {
            *(float2*)(rowA + nt * 8) = make_float2(acc[mt][nt][0], acc[mt][nt][1]);
            *(float2*)(rowB + nt * 8) = make_float2(acc[mt][nt][2], acc[mt][nt][3]);
        }
    }
}

// ---------------------------------------------------------------------------
// GEMM2: 2-term split (AhBh + AlBh), paired A + HI-ONLY B (half traffic).
// A tile 128xTP(48), B tile 128xTPB(24). NCH=32. Fused BN epilogue.
// ---------------------------------------------------------------------------
#define TPB   24
#define STGF2 (128 * TP + 128 * TPB)       // floats per stage
#define GEMM2_SMEM (2 * STGF2 * 4)         // 73728 bytes

__global__ __launch_bounds__(256, 2)
void gemm2_hi(const float* __restrict__ Ap, const float* __restrict__ Bp,
              float* __restrict__ C,
              const float* __restrict__ gamma, const float* __restrict__ beta,
              const float* __restrict__ mean,  const float* __restrict__ var)
{
    extern __shared__ float sm[];
    const int tid  = threadIdx.x;
    const int wid  = tid >> 5;
    const int lane = tid & 31;
    const int g    = lane >> 2;
    const int tig  = lane & 3;

    const int n0 = blockIdx.x * 128;
    const int m0 = blockIdx.y * 128;
    const int z  = blockIdx.z;

    const int wm = (wid & 3) * 32;
    const int wn = (wid >> 2) * 64;

    constexpr int NCH = 32;
    constexpr int K2A = NCH * 32;           // 1024 floats per A row
    constexpr int K2B = NCH * 16;           // 512 floats per B row
    const float* Bb = Bp + (size_t)z * HW * (size_t)K2B;
    float*       Cb = C  + (size_t)z * OC_OUT * HW;

    uint32_t smb;
    asm("{ .reg .u64 t; cvta.to.shared.u64 t, %1; cvt.u32.u64 %0, t; }" : "=r"(smb) : "l"(sm));

    // A fill: frow=tid>>3 (+32*it, 4 its), 16B block u8=tid&7
    const int frowA = tid >> 3;
    const int u8    = tid & 7;
    const float* gA = Ap + (size_t)(m0 + frowA) * K2A + u8 * 4;
    const uint32_t sA = smb + (uint32_t)(frowA * TP + u8 * 4) * 4u;
    // B fill: frowB=tid>>2 (+64*it, 2 its), 16B block u4=tid&3
    const int frowB = tid >> 2;
    const int u4    = tid & 3;
    const float* gB = Bb + (size_t)(n0 + frowB) * K2B + u4 * 4;
    const uint32_t sB = smb + (uint32_t)(128 * TP) * 4u
                            + (uint32_t)(frowB * TPB + u4 * 4) * 4u;

    float acc[2][8][4];
    #pragma unroll
    for (int mt = 0; mt < 2; mt++)
        #pragma unroll
        for (int nt = 0; nt < 8; nt++)
            #pragma unroll
            for (int j = 0; j < 4; j++) acc[mt][nt][j] = 0.f;

    #pragma unroll
    for (int it = 0; it < 4; it++)
        CP_ASYNC16(sA + (uint32_t)(it * 32 * TP) * 4u, gA + (size_t)it * 32 * K2A);
    #pragma unroll
    for (int it = 0; it < 2; it++)
        CP_ASYNC16(sB + (uint32_t)(it * 64 * TPB) * 4u, gB + (size_t)it * 64 * K2B);
    CP_COMMIT();

    #pragma unroll 2
    for (int c = 0; c < NCH; c++) {
        CP_WAIT_ALL();
        __syncthreads();
        if (c + 1 < NCH) {
            const uint32_t so = (uint32_t)(((c + 1) & 1)) * (STGF2 * 4u);
            #pragma unroll
            for (int it = 0; it < 4; it++)
                CP_ASYNC16(sA + so + (uint32_t)(it * 32 * TP) * 4u,
                           gA + (size_t)it * 32 * K2A + (c + 1) * 32);
            #pragma unroll
            for (int it = 0; it < 2; it++)
                CP_ASYNC16(sB + so + (uint32_t)(it * 64 * TPB) * 4u,
                           gB + (size_t)it * 64 * K2B + (c + 1) * 16);
            CP_COMMIT();
        }
        const float* As_ = sm + (c & 1) * STGF2;
        const float* Bs_ = As_ + 128 * TP;

        #pragma unroll
        for (int ks = 0; ks < 2; ks++) {
            const int colA = ks * 16 + tig * 4;
            const int colB = ks * 8 + tig * 2;
            float4 r1 = *(const float4*)(As_ + (wm + g     ) * TP + colA);
            float4 r2 = *(const float4*)(As_ + (wm + 8  + g) * TP + colA);
            float4 r3 = *(const float4*)(As_ + (wm + 16 + g) * TP + colA);
            float4 r4 = *(const float4*)(As_ + (wm + 24 + g) * TP + colA);
            uint32_t ahi0[4] = { __float_as_uint(r1.x), __float_as_uint(r2.x),
                                 __float_as_uint(r1.z), __float_as_uint(r2.z) };
            uint32_t alo0[4] = { __float_as_uint(r1.y), __float_as_uint(r2.y),
                                 __float_as_uint(r1.w), __float_as_uint(r2.w) };
            uint32_t ahi1[4] = { __float_as_uint(r3.x), __float_as_uint(r4.x),
                                 __float_as_uint(r3.z), __float_as_uint(r4.z) };
            uint32_t alo1[4] = { __float_as_uint(r3.y), __float_as_uint(r4.y),
                                 __float_as_uint(r3.w), __float_as_uint(r4.w) };
            #pragma unroll
            for (int nt = 0; nt < 8; nt++) {
                float2 rb = *(const float2*)(Bs_ + (wn + nt * 8 + g) * TPB + colB);
                uint32_t bh[2] = { __float_as_uint(rb.x), __float_as_uint(rb.y) };
                mma_tf32(acc[0][nt], alo0, bh);
                mma_tf32(acc[1][nt], alo1, bh);
                mma_tf32(acc[0][nt], ahi0, bh);
                mma_tf32(acc[1][nt], ahi1, bh);
            }
        }
    }

    #pragma unroll
    for (int mt = 0; mt < 2; mt++) {
        const int mA = m0 + wm + mt * 16 + g;
        const int mB = mA + 8;
        const float invA = gamma[mA] * rsqrtf(var[mA] + 1e-5f);
        const float invB = gamma[mB] * rsqrtf(var[mB] + 1e-5f);
        const float hA = beta[mA] - mean[mA] * invA;
        const float hB = beta[mB] - mean[mB] * invB;
        float* rowA = Cb + (size_t)mA * HW + n0 + wn + 2 * tig;
        float* rowB = Cb + (size_t)mB * HW + n0 + wn + 2 * tig;
        #pragma unroll
        for (int nt = 0; nt < 8; nt++) {
            *(float2*)(rowA + nt * 8) =
                make_float2(acc[mt][nt][0] * invA + hA, acc[mt][nt][1] * invA + hA);
            *(float2*)(rowB + nt * 8) =
                make_float2(acc[mt][nt][2] * invB + hB, acc[mt][nt][3] * invB + hB);
        }
    }
}

// ---------------------------------------------------------------------------
// Transpose x: [b][k=256][n] -> paired xt [b][n][16][32]
// ---------------------------------------------------------------------------
__global__ __launch_bounds__(256)
void transpose_kernel(const float* __restrict__ in, float* __restrict__ outp)
{
    __shared__ float t[32][33];
    const int b  = blockIdx.z;
    const int n0 = blockIdx.x * 32;
    const int k0 = blockIdx.y * 32;
    const int tx = threadIdx.x & 31;
    const int ty = threadIdx.x >> 5;

    const float* ib = in + (size_t)b * CIN * HW;
    float* ob = outp + (size_t)b * HW * (2 * CIN);

    #pragma unroll
    for (int i = 0; i < 4; i++) {
        const int k = k0 + ty + i * 8;
        t[ty + i * 8][tx] = ib[(size_t)k * HW + n0 + tx];
    }
    __syncthreads();
    #pragma unroll
    for (int i = 0; i < 4; i++) {
        const int n = n0 + ty + i * 8;
        const int k = k0 + tx;
        const float v = t[tx][ty + i * 8];
        const float h = tf32r(v);
        float* dst = ob + (size_t)n * (2 * CIN) + (k >> 4) * 32 + pair16(k & 15);
        dst[0] = h;
        dst[1] = tf32r(v - h);
    }
}

// ---------------------------------------------------------------------------
// Fused depthwise 3x3 + grouped 1x1
// ---------------------------------------------------------------------------
__global__ __launch_bounds__(256)
void dwpw_kernel(const float* __restrict__ qkv,
                 const float* __restrict__ wdw,
                 const float* __restrict__ wpw,
                 float* __restrict__ agg)
{
    const int strip = blockIdx.x;
    const int gg    = blockIdx.y;
    const int b     = blockIdx.z;
    const int r0    = strip * 16;

    __shared__ float s_in[8][18][68];
    __shared__ float s_wdw[8][9];
    __shared__ float s_wpw[8][8];

    const int tid = threadIdx.x;
    const float* base = qkv + ((size_t)b * OC_QKV + gg * 8) * HW;

    for (int idx = tid; idx < 8 * 18 * 16; idx += 256) {
        const int seg = idx & 15;
        const int row = idx >> 4;
        const int rr  = row % 18;
        const int ch  = row / 18;
        const int y   = r0 + rr - 1;
        float4 v = make_float4(0.f, 0.f, 0.f, 0.f);
        if (y >= 0 && y < HH)
            v = *(const float4*)(base + (size_t)ch * HW + y * WW + seg * 4);
        float* d = &s_in[ch][rr][1 + seg * 4];
        d[0] = v.x; d[1] = v.y; d[2] = v.z; d[3] = v.w;
        if (seg == 0)  s_in[ch][rr][0]  = 0.f;
        if (seg == 15) s_in[ch][rr][65] = 0.f;
    }
    if (tid < 72)
        s_wdw[tid / 9][tid % 9] = wdw[(size_t)(gg * 8 + tid / 9) * 9 + tid % 9];
    if (tid >= 128 && tid < 192) {
        int t = tid - 128;
        s_wpw[t >> 3][t & 7] = wpw[(size_t)(gg * 8 + (t >> 3)) * 8 + (t & 7)];
    }
    __syncthreads();

    float* obase = agg + ((size_t)b * OC_QKV + gg * 8) * HW + r0 * WW;
    for (int p = tid; p < 16 * WW; p += 256) {
        const int py = p >> 6;
        const int px = p & 63;
        float dwv[8];
        #pragma unroll
        for (int ic = 0; ic < 8; ic++) {
            float s = 0.f;
            #pragma unroll
            for (int ky = 0; ky < 3; ky++)
                #pragma unroll
                for (int kx = 0; kx < 3; kx++)
                    s += s_in[ic][py + ky][px + kx] * s_wdw[ic][ky * 3 + kx];
            dwv[ic] = s;
        }
        #pragma unroll
        for (int oc = 0; oc < 8; oc++) {
            float s = 0.f;
            #pragma unroll
            for (int ic = 0; ic < 8; ic++) s += s_wpw[oc][ic] * dwv[ic];
            obase[(size_t)oc * HW + p] = s;
        }
    }
}

// ---------------------------------------------------------------------------
// kv partial reduction over 4 n-segments
// ---------------------------------------------------------------------------
__global__ __launch_bounds__(256)
void kv_kernel(const float* __restrict__ qkv, const float* __restrict__ agg,
               float* __restrict__ kvout)
{
    const int h   = blockIdx.x;
    const int b   = blockIdx.y;
    const int seg = blockIdx.z;
    const float* src = (h < 32) ? qkv : agg;
    const int ch0 = (h & 31) * 24;
    const float* base = src + ((size_t)b * OC_QKV + ch0) * HW;

    float acc[8][9];
    #pragma unroll
    for (int d = 0; d < 8; d++)
        #pragma unroll
        for (int e = 0; e < 9; e++) acc[d][e] = 0.f;

    const int nend = (seg + 1) * 1024;
    for (int n = seg * 1024 + threadIdx.x; n < nend; n += 256) {
        float kk[8], vv[8];
        #pragma unroll
        for (int d = 0; d < 8; d++)
            kk[d] = fmaxf(base[(size_t)(8 + d) * HW + n], 0.f);
        #pragma unroll
        for (int e = 0; e < 8; e++)
            vv[e] = base[(size_t)(16 + e) * HW + n];
        #pragma unroll
        for (int d = 0; d < 8; d++) {
            #pragma unroll
            for (int e = 0; e < 8; e++) acc[d][e] += kk[d] * vv[e];
            acc[d][8] += kk[d];
        }
    }

    __shared__ float sred[8][72];
    const int lane = threadIdx.x & 31;
    const int warp = threadIdx.x >> 5;
    #pragma unroll
    for (int d = 0; d < 8; d++)
        #pragma unroll
        for (int e = 0; e < 9; e++) {
            float v = acc[d][e];
            #pragma unroll
            for (int o = 16; o > 0; o >>= 1)
                v += __shfl_down_sync(0xffffffffu, v, o);
            if (lane == 0) sred[warp][d * 9 + e] = v;
        }
    __syncthreads();
    if (threadIdx.x < 72) {
        float s = 0.f;
        #pragma unroll
        for (int w = 0; w < 8; w++) s += sred[w][threadIdx.x];
        kvout[(((size_t)b * HEADS + h) * 4 + seg) * 72 + threadIdx.x] = s;
    }
}

// ---------------------------------------------------------------------------
// attention apply -> hi-only att [b][n][512] in frag order:
//   chunk = c>>4 (16 floats), in-chunk off(kk)=(kk>>3)*8+(kk&3)*2+((kk>>2)&1)
//   head h -> chunk h>>1, 8-float subblock (h&1)*8, order [d0,d4,d1,d5,d2,d6,d3,d7]
// ---------------------------------------------------------------------------
__global__ __launch_bounds__(256)
void apply_kernel(const float* __restrict__ qkv, const float* __restrict__ agg,
                  const float* __restrict__ kvin, float* __restrict__ attp)
{
    const int h = blockIdx.x;
    const int b = blockIdx.y;
    const float* src = (h < 32) ? qkv : agg;
    const int ch0 = (h & 31) * 24;
    const float* qb = src + ((size_t)b * OC_QKV + ch0) * HW;

    __shared__ float s_kv[72];
    if (threadIdx.x < 72) {
        const float* kp = kvin + ((size_t)b * HEADS + h) * 4 * 72 + threadIdx.x;
        s_kv[threadIdx.x] = kp[0] + kp[72] + kp[144] + kp[216];
    }
    __syncthreads();

    float* ob = attp + (size_t)b * HW * ATT_CH + (h >> 1) * 16 + (h & 1) * 8;
    for (int n = threadIdx.x; n < HW; n += 256) {
        float q[8];
        #pragma unroll
        for (int d = 0; d < 8; d++)
            q[d] = fmaxf(qb[(size_t)d * HW + n], 0.f);
        float num[9];
        #pragma unroll
        for (int e = 0; e < 9; e++) {
            float s = 0.f;
            #pragma unroll
            for (int d = 0; d < 8; d++) s += q[d] * s_kv[d * 9 + e];
            num[e] = s;
        }
        const float r = 1.0f / (num[8] + 1e-15f);
        float hv[8];
        #pragma unroll
        for (int d = 0; d < 8; d++)
            hv[d] = tf32r(num[d] * r);
        float* dst = ob + (size_t)n * ATT_CH;
        *(float4*)(dst + 0) = make_float4(hv[0], hv[4], hv[1], hv[5]);
        *(float4*)(dst + 4) = make_float4(hv[2], hv[6], hv[3], hv[7]);
    }
}

// ---------------------------------------------------------------------------
// Launch
// ---------------------------------------------------------------------------
extern "C" void kernel_launch(void* const* d_in, const int* in_sizes, int n_in,
                              void* d_out, int out_size)
{
    const float* x      = (const float*)d_in[0];
    const float* w_qkv  = (const float*)d_in[1];
    const float* w_dw   = (const float*)d_in[2];
    const float* w_pw   = (const float*)d_in[3];
    const float* w_proj = (const float*)d_in[4];
    const float* gamma  = (const float*)d_in[5];
    const float* beta   = (const float*)d_in[6];
    const float* mean   = (const float*)d_in[7];
    const float* var    = (const float*)d_in[8];
    float* out = (float*)d_out;

    float *qkv_p, *agg_p, *kv_p, *attp_p, *xtp_p, *wqp_p, *wpp_p;
    cudaGetSymbolAddress((void**)&qkv_p,  g_qkv);
    cudaGetSymbolAddress((void**)&agg_p,  g_agg);
    cudaGetSymbolAddress((void**)&kv_p,   g_kv);
    cudaGetSymbolAddress((void**)&attp_p, g_attp);
    cudaGetSymbolAddress((void**)&xtp_p,  g_xtp);
    cudaGetSymbolAddress((void**)&wqp_p,  g_wqp);
    cudaGetSymbolAddress((void**)&wpp_p,  g_wpp);

    cudaFuncSetAttribute(gemm_pair<16>, cudaFuncAttributeMaxDynamicSharedMemorySize, GEMM_SMEM);
    cudaFuncSetAttribute(gemm2_hi, cudaFuncAttributeMaxDynamicSharedMemorySize, GEMM2_SMEM);

    split_kernel<<<(OC_QKV * CIN + 255) / 256, 256>>>(w_qkv, wqp_p, OC_QKV, CIN);
    split_kernel<<<(OC_OUT * K_PROJ + 255) / 256, 256>>>(w_proj, wpp_p, OC_OUT, K_PROJ);
    {
        dim3 grid(HW / 32, CIN / 32, BATCH);
        transpose_kernel<<<grid, 256>>>(x, xtp_p);
    }
    // 1) qkv = W_qkv * x : 3-term (feeds amplifying chain)
    {
        dim3 grid(HW / 128, OC_QKV / 128, BATCH);
        gemm_pair<16><<<grid, 256, GEMM_SMEM>>>(wqp_p, xtp_p, qkv_p, OC_QKV);
    }
    // 2) depthwise + grouped pointwise
    {
        dim3 grid(4, 96, BATCH);
        dwpw_kernel<<<grid, 256>>>(qkv_p, w_dw, w_pw, agg_p);
    }
    // 3) kv partial reduction
    {
        dim3 grid(HEADS, BATCH, 4);
        kv_kernel<<<grid, 256>>>(qkv_p, agg_p, kv_p);
    }
    // 4) attention apply (hi-only att)
    {
        dim3 grid(HEADS, BATCH);
        apply_kernel<<<grid, 256>>>(qkv_p, agg_p, kv_p, attp_p);
    }
    // 5) y = W_proj * att + BN : 2-term, hi-only B
    {
        dim3 grid(HW / 128, OC_OUT / 128, BATCH);
        gemm2_hi<<<grid, 256, GEMM2_SMEM>>>(wpp_p, attp_p, out,
                                            gamma, beta, mean, var);
    }
}